// round 1
// baseline (speedup 1.0000x reference)
#include <cuda_runtime.h>
#include <cuda_bf16.h>

// Problem constants
#define Bsz 2
#define Tlen 2048
#define Cdim 1024
#define NH 16
#define HS 64
#define M_ROWS (Bsz * Tlen)        // 4096
#define N_QKV (3 * Cdim)           // 3072

// Scratch (no cudaMalloc allowed)
__device__ float g_Q[Bsz * NH * Tlen * HS];
__device__ float g_K[Bsz * NH * Tlen * HS];
__device__ float g_V[Bsz * NH * Tlen * HS];
__device__ float g_Y[M_ROWS * Cdim];

// ---------------------------------------------------------------------------
// Kernel 1: QKV GEMM (x @ W_qkv + b) fused with RoPE and scatter to Q/K/V
// 128x128 tile, K-step 8, 256 threads, 8x8 micro-tile
// ---------------------------------------------------------------------------
__global__ __launch_bounds__(256) void qkv_gemm_rope(
    const float* __restrict__ x,      // [4096,1024]
    const float* __restrict__ W,      // [1024,3072]
    const float* __restrict__ bias)   // [3072]
{
    const int K = Cdim;
    const int N = N_QKV;
    __shared__ float As[8][128];
    __shared__ float Bs[8][128];

    int tid = threadIdx.x;
    int tx = tid & 15;
    int ty = tid >> 4;
    int block_m = blockIdx.y * 128;
    int block_n = blockIdx.x * 128;

    int a_row = tid >> 1;          // 0..127
    int a_col = (tid & 1) * 4;     // 0 or 4
    int b_row = tid >> 5;          // 0..7
    int b_col = (tid & 31) * 4;    // 0..124

    float acc[8][8];
#pragma unroll
    for (int i = 0; i < 8; i++)
#pragma unroll
        for (int j = 0; j < 8; j++) acc[i][j] = 0.0f;

    for (int k0 = 0; k0 < K; k0 += 8) {
        float4 av = *(const float4*)&x[(long)(block_m + a_row) * K + k0 + a_col];
        As[a_col + 0][a_row] = av.x;
        As[a_col + 1][a_row] = av.y;
        As[a_col + 2][a_row] = av.z;
        As[a_col + 3][a_row] = av.w;
        float4 bv = *(const float4*)&W[(long)(k0 + b_row) * N + block_n + b_col];
        *(float4*)&Bs[b_row][b_col] = bv;
        __syncthreads();
#pragma unroll
        for (int k = 0; k < 8; k++) {
            float4 a0 = *(float4*)&As[k][ty * 8];
            float4 a1 = *(float4*)&As[k][ty * 8 + 4];
            float4 b0 = *(float4*)&Bs[k][tx * 8];
            float4 b1 = *(float4*)&Bs[k][tx * 8 + 4];
            float am[8] = {a0.x, a0.y, a0.z, a0.w, a1.x, a1.y, a1.z, a1.w};
            float bn[8] = {b0.x, b0.y, b0.z, b0.w, b1.x, b1.y, b1.z, b1.w};
#pragma unroll
            for (int i = 0; i < 8; i++)
#pragma unroll
                for (int j = 0; j < 8; j++) acc[i][j] = fmaf(am[i], bn[j], acc[i][j]);
        }
        __syncthreads();
    }

    // Epilogue: bias + RoPE (q,k) + scatter into [B*H, T, HS]
    int m0 = block_m + ty * 8;
    int n0 = block_n + tx * 8;
#pragma unroll
    for (int i = 0; i < 8; i++) {
        int m = m0 + i;
        int b = m >> 11;       // /2048
        int t = m & 2047;
#pragma unroll
        for (int jp = 0; jp < 8; jp += 2) {
            int n = n0 + jp;
            float v0 = acc[i][jp] + bias[n];
            float v1 = acc[i][jp + 1] + bias[n + 1];
            int h = n / 192;
            int r = n - h * 192;     // 0..190, even
            if (r < 128) {
                int p = (r & 63) >> 1;                 // pair index 0..31
                float theta = __expf(-(float)p * 0.28782313662425572f); // ln(1e4)/32
                float ang = (float)t * theta;
                float s, c;
                sincosf(ang, &s, &c);
                float r0 = v0 * c - v1 * s;
                float r1 = v0 * s + v1 * c;
                v0 = r0; v1 = r1;
            }
            int d = r & 63;
            float* base = (r < 64) ? g_Q : ((r < 128) ? g_K : g_V);
            long idx = (((long)(b * NH + h) * Tlen) + t) * HS + d;
            base[idx] = v0;
            base[idx + 1] = v1;
        }
    }
}

// ---------------------------------------------------------------------------
// Kernel 2: causal flash attention, 64 queries per block, 64-key tiles,
// 256 threads (16x16, 4x4 micro-tiles), online softmax.
// ---------------------------------------------------------------------------
#define QS_STRIDE 68
#define PS_STRIDE 68
// smem floats: Qs 64*68 + Ks 64*68 + Vs 64*64 + Ps 64*68 + 192 aux = 17344
#define ATTN_SMEM_FLOATS (64 * QS_STRIDE * 2 + 64 * 64 + 64 * PS_STRIDE + 192)

__global__ __launch_bounds__(256) void attn_kernel(
    const float* __restrict__ Q,
    const float* __restrict__ K,
    const float* __restrict__ V,
    float* __restrict__ Y)
{
    extern __shared__ float sm[];
    float* Qs = sm;                          // [d][m] stride 68
    float* Ks = Qs + 64 * QS_STRIDE;         // [d][n] stride 68
    float* Vs = Ks + 64 * QS_STRIDE;         // [n][d] stride 64
    float* Ps = Vs + 64 * 64;                // [m][n] stride 68
    float* m_sh = Ps + 64 * PS_STRIDE;
    float* l_sh = m_sh + 64;
    float* corr = l_sh + 64;

    int tid = threadIdx.x;
    int tx = tid & 15;
    int ty = tid >> 4;
    int warp = tid >> 5;
    int lane = tid & 31;

    int qtile = blockIdx.x;
    int bh = blockIdx.y;

    const float* Qg = Q + ((long)bh * Tlen + qtile * 64) * HS;

    // Load Q tile transposed, fold in softmax scale 1/sqrt(64)=0.125
    for (int idx = tid; idx < 4096; idx += 256) {
        int mm = idx >> 6, dd = idx & 63;
        Qs[dd * QS_STRIDE + mm] = Qg[idx] * 0.125f;
    }
    if (tid < 64) { m_sh[tid] = -1e30f; l_sh[tid] = 0.0f; }

    float o[4][4];
#pragma unroll
    for (int i = 0; i < 4; i++)
#pragma unroll
        for (int j = 0; j < 4; j++) o[i][j] = 0.0f;

    __syncthreads();

    for (int kt = 0; kt <= qtile; ++kt) {
        const float* Kg = K + ((long)bh * Tlen + kt * 64) * HS;
        const float* Vg = V + ((long)bh * Tlen + kt * 64) * HS;
        for (int idx = tid; idx < 4096; idx += 256) {
            int nn = idx >> 6, dd = idx & 63;
            Ks[dd * QS_STRIDE + nn] = Kg[idx];
            Vs[idx] = Vg[idx];
        }
        __syncthreads();

        // S = Q K^T  (each thread: m = ty*4+i, n = tx*4+j)
        float s[4][4];
#pragma unroll
        for (int i = 0; i < 4; i++)
#pragma unroll
            for (int j = 0; j < 4; j++) s[i][j] = 0.0f;
#pragma unroll 4
        for (int d = 0; d < 64; ++d) {
            float4 qa = *(float4*)&Qs[d * QS_STRIDE + ty * 4];
            float4 kb = *(float4*)&Ks[d * QS_STRIDE + tx * 4];
            float qv[4] = {qa.x, qa.y, qa.z, qa.w};
            float kv[4] = {kb.x, kb.y, kb.z, kb.w};
#pragma unroll
            for (int i = 0; i < 4; i++)
#pragma unroll
                for (int j = 0; j < 4; j++) s[i][j] = fmaf(qv[i], kv[j], s[i][j]);
        }

        bool diag = (kt == qtile);
#pragma unroll
        for (int i = 0; i < 4; i++) {
            int m = ty * 4 + i;
            float4 row;
            float* rp = &row.x;
#pragma unroll
            for (int j = 0; j < 4; j++) {
                int n = tx * 4 + j;
                float v = s[i][j];
                if (diag && n > m) v = -1e30f;
                rp[j] = v;
            }
            *(float4*)&Ps[m * PS_STRIDE + tx * 4] = row;
        }
        __syncthreads();

        // Online softmax: warp w owns rows w*8 .. w*8+7
#pragma unroll
        for (int rr = 0; rr < 8; ++rr) {
            int m = warp * 8 + rr;
            float2 sv = *(float2*)&Ps[m * PS_STRIDE + lane * 2];
            float mx = fmaxf(sv.x, sv.y);
#pragma unroll
            for (int off = 16; off; off >>= 1)
                mx = fmaxf(mx, __shfl_xor_sync(0xffffffffu, mx, off));
            float mold = m_sh[m];
            float mnew = fmaxf(mold, mx);
            float e0 = __expf(sv.x - mnew);
            float e1 = __expf(sv.y - mnew);
            *(float2*)&Ps[m * PS_STRIDE + lane * 2] = make_float2(e0, e1);
            float sum = e0 + e1;
#pragma unroll
            for (int off = 16; off; off >>= 1)
                sum += __shfl_xor_sync(0xffffffffu, sum, off);
            if (lane == 0) {
                float cf = __expf(mold - mnew);
                l_sh[m] = l_sh[m] * cf + sum;
                m_sh[m] = mnew;
                corr[m] = cf;
            }
        }
        __syncthreads();

        // Rescale accumulators, then O += P V
#pragma unroll
        for (int i = 0; i < 4; i++) {
            float cf = corr[ty * 4 + i];
#pragma unroll
            for (int j = 0; j < 4; j++) o[i][j] *= cf;
        }
#pragma unroll 4
        for (int n = 0; n < 64; ++n) {
            float4 vb = *(float4*)&Vs[n * 64 + tx * 4];
            float vv[4] = {vb.x, vb.y, vb.z, vb.w};
            float pv[4];
#pragma unroll
            for (int i = 0; i < 4; i++) pv[i] = Ps[(ty * 4 + i) * PS_STRIDE + n];
#pragma unroll
            for (int i = 0; i < 4; i++)
#pragma unroll
                for (int j = 0; j < 4; j++) o[i][j] = fmaf(pv[i], vv[j], o[i][j]);
        }
        __syncthreads();
    }

    // Finalize: Y[b, t, h*64+d] = O / l
    int b = bh >> 4, h = bh & 15;
#pragma unroll
    for (int i = 0; i < 4; i++) {
        int m = ty * 4 + i;
        int t = qtile * 64 + m;
        float inv = 1.0f / l_sh[m];
        long base = ((long)b * Tlen + t) * Cdim + h * HS + tx * 4;
#pragma unroll
        for (int j = 0; j < 4; j++)
            Y[base + j] = o[i][j] * inv;
    }
}

// ---------------------------------------------------------------------------
// Kernel 3: proj GEMM (Y @ W_proj + b_proj) -> out
// ---------------------------------------------------------------------------
__global__ __launch_bounds__(256) void proj_gemm(
    const float* __restrict__ A,     // [4096,1024]
    const float* __restrict__ W,     // [1024,1024]
    const float* __restrict__ bias,  // [1024]
    float* __restrict__ out)         // [4096,1024]
{
    const int K = Cdim;
    const int N = Cdim;
    __shared__ float As[8][128];
    __shared__ float Bs[8][128];

    int tid = threadIdx.x;
    int tx = tid & 15;
    int ty = tid >> 4;
    int block_m = blockIdx.y * 128;
    int block_n = blockIdx.x * 128;

    int a_row = tid >> 1;
    int a_col = (tid & 1) * 4;
    int b_row = tid >> 5;
    int b_col = (tid & 31) * 4;

    float acc[8][8];
#pragma unroll
    for (int i = 0; i < 8; i++)
#pragma unroll
        for (int j = 0; j < 8; j++) acc[i][j] = 0.0f;

    for (int k0 = 0; k0 < K; k0 += 8) {
        float4 av = *(const float4*)&A[(long)(block_m + a_row) * K + k0 + a_col];
        As[a_col + 0][a_row] = av.x;
        As[a_col + 1][a_row] = av.y;
        As[a_col + 2][a_row] = av.z;
        As[a_col + 3][a_row] = av.w;
        float4 bv = *(const float4*)&W[(long)(k0 + b_row) * N + block_n + b_col];
        *(float4*)&Bs[b_row][b_col] = bv;
        __syncthreads();
#pragma unroll
        for (int k = 0; k < 8; k++) {
            float4 a0 = *(float4*)&As[k][ty * 8];
            float4 a1 = *(float4*)&As[k][ty * 8 + 4];
            float4 b0 = *(float4*)&Bs[k][tx * 8];
            float4 b1 = *(float4*)&Bs[k][tx * 8 + 4];
            float am[8] = {a0.x, a0.y, a0.z, a0.w, a1.x, a1.y, a1.z, a1.w};
            float bn[8] = {b0.x, b0.y, b0.z, b0.w, b1.x, b1.y, b1.z, b1.w};
#pragma unroll
            for (int i = 0; i < 8; i++)
#pragma unroll
                for (int j = 0; j < 8; j++) acc[i][j] = fmaf(am[i], bn[j], acc[i][j]);
        }
        __syncthreads();
    }

    int m0 = block_m + ty * 8;
    int n0 = block_n + tx * 8;
#pragma unroll
    for (int i = 0; i < 8; i++) {
        long rowbase = (long)(m0 + i) * N;
#pragma unroll
        for (int j = 0; j < 8; j += 4) {
            int n = n0 + j;
            float4 v;
            v.x = acc[i][j + 0] + bias[n + 0];
            v.y = acc[i][j + 1] + bias[n + 1];
            v.z = acc[i][j + 2] + bias[n + 2];
            v.w = acc[i][j + 3] + bias[n + 3];
            *(float4*)&out[rowbase + n] = v;
        }
    }
}

// ---------------------------------------------------------------------------
extern "C" void kernel_launch(void* const* d_in, const int* in_sizes, int n_in,
                              void* d_out, int out_size)
{
    const float* x      = (const float*)d_in[0];
    const float* W_qkv  = (const float*)d_in[1];
    const float* b_qkv  = (const float*)d_in[2];
    const float* W_proj = (const float*)d_in[3];
    const float* b_proj = (const float*)d_in[4];
    float* out = (float*)d_out;

    float *Qp, *Kp, *Vp, *Yp;
    cudaGetSymbolAddress((void**)&Qp, g_Q);
    cudaGetSymbolAddress((void**)&Kp, g_K);
    cudaGetSymbolAddress((void**)&Vp, g_V);
    cudaGetSymbolAddress((void**)&Yp, g_Y);

    static int smem_set = 0;
    int attn_smem = ATTN_SMEM_FLOATS * (int)sizeof(float);
    if (!smem_set) {
        cudaFuncSetAttribute(attn_kernel, cudaFuncAttributeMaxDynamicSharedMemorySize, attn_smem);
        smem_set = 1;
    }

    dim3 g1(N_QKV / 128, M_ROWS / 128);
    qkv_gemm_rope<<<g1, 256>>>(x, W_qkv, b_qkv);

    dim3 g2(Tlen / 64, Bsz * NH);
    attn_kernel<<<g2, 256, attn_smem>>>(Qp, Kp, Vp, Yp);

    dim3 g3(Cdim / 128, M_ROWS / 128);
    proj_gemm<<<g3, 256>>>(Yp, W_proj, b_proj, out);
}

// round 3
// speedup vs baseline: 1.4580x; 1.4580x over previous
#include <cuda_runtime.h>
#include <cuda_bf16.h>
#include <stdint.h>

// Problem constants
#define Bsz 2
#define Tlen 2048
#define Cdim 1024
#define NH 16
#define HS 64
#define M_ROWS (Bsz * Tlen)        // 4096
#define N_QKV (3 * Cdim)           // 3072

// ---------------------------------------------------------------------------
// Device scratch (no cudaMalloc allowed)
// ---------------------------------------------------------------------------
__device__ float g_Q[Bsz * NH * Tlen * HS];
__device__ float g_K[Bsz * NH * Tlen * HS];
__device__ float g_V[Bsz * NH * Tlen * HS];
__device__ float g_Y[M_ROWS * Cdim];

__device__ __nv_bfloat16 g_xhi[M_ROWS * Cdim];
__device__ __nv_bfloat16 g_xlo[M_ROWS * Cdim];
__device__ __nv_bfloat16 g_wqkv_hi[N_QKV * Cdim];   // transposed [N][K]
__device__ __nv_bfloat16 g_wqkv_lo[N_QKV * Cdim];
__device__ __nv_bfloat16 g_wproj_hi[Cdim * Cdim];   // transposed [N][K]
__device__ __nv_bfloat16 g_wproj_lo[Cdim * Cdim];
__device__ __nv_bfloat16 g_yhi[M_ROWS * Cdim];
__device__ __nv_bfloat16 g_ylo[M_ROWS * Cdim];

// ---------------------------------------------------------------------------
// Portable PTX helpers (no arch-specific 'a' features!)
// ---------------------------------------------------------------------------
__device__ __forceinline__ uint32_t smem_u32(const void* p) {
    uint32_t a;
    asm("{ .reg .u64 t; cvta.to.shared.u64 t, %1; cvt.u32.u64 %0, t; }"
        : "=r"(a) : "l"(p));
    return a;
}
__device__ __forceinline__ void cp16(uint32_t s, const void* g) {
    asm volatile("cp.async.cg.shared.global [%0], [%1], 16;" :: "r"(s), "l"(g));
}
__device__ __forceinline__ void cp_commit() {
    asm volatile("cp.async.commit_group;" ::: "memory");
}
__device__ __forceinline__ void cp_wait1() {
    asm volatile("cp.async.wait_group 1;" ::: "memory");
}
__device__ __forceinline__ void cp_wait0() {
    asm volatile("cp.async.wait_group 0;" ::: "memory");
}
__device__ __forceinline__ void ldm_x4(uint32_t* r, uint32_t addr) {
    asm volatile("ldmatrix.sync.aligned.m8n8.x4.shared.b16 {%0,%1,%2,%3}, [%4];"
                 : "=r"(r[0]), "=r"(r[1]), "=r"(r[2]), "=r"(r[3]) : "r"(addr));
}
__device__ __forceinline__ void ldm_x2(uint32_t* r, uint32_t addr) {
    asm volatile("ldmatrix.sync.aligned.m8n8.x2.shared.b16 {%0,%1}, [%2];"
                 : "=r"(r[0]), "=r"(r[1]) : "r"(addr));
}
__device__ __forceinline__ void mma16816(float* c, const uint32_t* a, const uint32_t* b) {
    asm volatile(
        "mma.sync.aligned.m16n8k16.row.col.f32.bf16.bf16.f32 "
        "{%0,%1,%2,%3}, {%4,%5,%6,%7}, {%8,%9}, {%0,%1,%2,%3};"
        : "+f"(c[0]), "+f"(c[1]), "+f"(c[2]), "+f"(c[3])
        : "r"(a[0]), "r"(a[1]), "r"(a[2]), "r"(a[3]), "r"(b[0]), "r"(b[1]));
}

// ---------------------------------------------------------------------------
// Prep kernels: fp32 -> bf16 hi/lo split (elementwise, and transposed for W)
// ---------------------------------------------------------------------------
__global__ __launch_bounds__(256) void split_bf16(
    const float* __restrict__ in, __nv_bfloat16* __restrict__ hi,
    __nv_bfloat16* __restrict__ lo, int n4)
{
    int i = blockIdx.x * 256 + threadIdx.x;
    if (i >= n4) return;
    float4 v = ((const float4*)in)[i];
    __nv_bfloat16 h0 = __float2bfloat16(v.x);
    __nv_bfloat16 h1 = __float2bfloat16(v.y);
    __nv_bfloat16 h2 = __float2bfloat16(v.z);
    __nv_bfloat16 h3 = __float2bfloat16(v.w);
    __nv_bfloat162* H = (__nv_bfloat162*)hi;
    __nv_bfloat162* L = (__nv_bfloat162*)lo;
    H[i * 2 + 0] = __nv_bfloat162(h0, h1);
    H[i * 2 + 1] = __nv_bfloat162(h2, h3);
    L[i * 2 + 0] = __nv_bfloat162(__float2bfloat16(v.x - __bfloat162float(h0)),
                                  __float2bfloat16(v.y - __bfloat162float(h1)));
    L[i * 2 + 1] = __nv_bfloat162(__float2bfloat16(v.z - __bfloat162float(h2)),
                                  __float2bfloat16(v.w - __bfloat162float(h3)));
}

// W [K][N] -> Wt hi/lo [N][K]
__global__ __launch_bounds__(256) void transpose_split(
    const float* __restrict__ W, __nv_bfloat16* __restrict__ hi,
    __nv_bfloat16* __restrict__ lo, int K, int N)
{
    __shared__ float t[32][33];
    int n0 = blockIdx.x * 32, k0 = blockIdx.y * 32;
    int tx = threadIdx.x, ty = threadIdx.y;
#pragma unroll
    for (int r = ty; r < 32; r += 8)
        t[r][tx] = W[(size_t)(k0 + r) * N + n0 + tx];
    __syncthreads();
#pragma unroll
    for (int r = ty; r < 32; r += 8) {
        float v = t[tx][r];  // W[k0+tx][n0+r]
        size_t o = (size_t)(n0 + r) * K + k0 + tx;
        __nv_bfloat16 h = __float2bfloat16(v);
        hi[o] = h;
        lo[o] = __float2bfloat16(v - __bfloat162float(h));
    }
}

// ---------------------------------------------------------------------------
// mma.sync GEMM: D[128m x 128n] = Ahi*Bhi + Ahi*Blo + Alo*Bhi  (K = 1024)
// 8 warps, warp tile 64x32, K-chunk 32, cp.async double buffer.
// Smem rows padded to 80B -> conflict-free ldmatrix (offsets mod 128 distinct).
// mode 0: bias + RoPE + scatter to g_Q/g_K/g_V    mode 1: bias + store out
// ---------------------------------------------------------------------------
#define ROWB 80
#define TILEB (128 * ROWB)          // 10240 per sub-tile
#define BUFB  (4 * TILEB)           // Ahi,Alo,Bhi,Blo = 40960
#define GEMM_SMEM (2 * BUFB)        // 81920

__global__ __launch_bounds__(256) void gemm_mma(
    const __nv_bfloat16* __restrict__ Ahi,
    const __nv_bfloat16* __restrict__ Alo,
    const __nv_bfloat16* __restrict__ Bhi,
    const __nv_bfloat16* __restrict__ Blo,
    const float* __restrict__ bias,
    float* __restrict__ outp,
    int mode)
{
    extern __shared__ __align__(128) char smc[];
    const uint32_t sbase = smem_u32(smc);
    const int tid = threadIdx.x;
    const int lane = tid & 31;
    const int wid = tid >> 5;
    const int warp_m = wid >> 2;      // 0..1
    const int warp_n = wid & 3;       // 0..3
    const int block_n = blockIdx.x * 128;
    const int block_m = blockIdx.y * 128;

    const char* srcs[4] = {
        (const char*)Ahi + (size_t)block_m * 2048,
        (const char*)Alo + (size_t)block_m * 2048,
        (const char*)Bhi + (size_t)block_n * 2048,
        (const char*)Blo + (size_t)block_n * 2048 };

    float acc[4][4][4];
#pragma unroll
    for (int i = 0; i < 4; i++)
#pragma unroll
        for (int j = 0; j < 4; j++)
#pragma unroll
            for (int k = 0; k < 4; k++) acc[i][j][k] = 0.0f;

    // --- async load of one K32 chunk into buffer ---
    auto load_chunk = [&](int c, int buf) {
        uint32_t db = sbase + buf * BUFB;
        size_t goff = (size_t)c * 64;
#pragma unroll
        for (int it = 0; it < 8; ++it) {
            int i = tid + it * 256;
            int tI = i >> 9;            // 0..3
            int r = (i >> 2) & 127;
            int seg = i & 3;
            cp16(db + tI * TILEB + r * ROWB + seg * 16,
                 srcs[tI] + (size_t)r * 2048 + goff + seg * 16);
        }
        cp_commit();
    };

    load_chunk(0, 0);

    for (int c = 0; c < 32; ++c) {
        int buf = c & 1;
        if (c + 1 < 32) { load_chunk(c + 1, (c + 1) & 1); cp_wait1(); }
        else cp_wait0();
        __syncthreads();

        uint32_t abase = sbase + buf * BUFB;
        uint32_t bbase = abase + 2 * TILEB;
#pragma unroll
        for (int k16 = 0; k16 < 2; ++k16) {
            uint32_t ah[4][4], al[4][4], bh[4][2], bl[4][2];
            int akb = k16 * 32 + ((lane >> 4) & 1) * 16;
            int bkb = k16 * 32 + ((lane >> 3) & 1) * 16;
#pragma unroll
            for (int mt = 0; mt < 4; ++mt) {
                int row = warp_m * 64 + mt * 16 + (lane & 15);
                uint32_t ad = abase + row * ROWB + akb;
                ldm_x4(ah[mt], ad);
                ldm_x4(al[mt], ad + TILEB);
            }
#pragma unroll
            for (int nt = 0; nt < 4; ++nt) {
                int nrow = warp_n * 32 + nt * 8 + (lane & 7);
                uint32_t bd = bbase + nrow * ROWB + bkb;
                ldm_x2(bh[nt], bd);
                ldm_x2(bl[nt], bd + TILEB);
            }
#pragma unroll
            for (int mt = 0; mt < 4; ++mt)
#pragma unroll
                for (int nt = 0; nt < 4; ++nt) {
                    mma16816(acc[mt][nt], ah[mt], bh[nt]);
                    mma16816(acc[mt][nt], ah[mt], bl[nt]);
                    mma16816(acc[mt][nt], al[mt], bh[nt]);
                }
        }
        __syncthreads();
    }

    // --- epilogue ---
    const int gid = lane >> 2;           // 0..7
    const int cpair = (lane & 3) * 2;    // even col within 8-tile

#pragma unroll
    for (int nt = 0; nt < 4; ++nt) {
        int n_g = block_n + warp_n * 32 + nt * 8 + cpair;
        float bi0 = bias[n_g], bi1 = bias[n_g + 1];
        int h = n_g / 192;
        int r = n_g - h * 192;
        // rope constants for this column pair (if applicable)
        float theta = 0.0f;
        bool do_rope = false;
        if (mode == 0 && r < 128) {
            int p = (r & 63) >> 1;
            theta = __expf(-(float)p * 0.28782313662425572f);
            do_rope = true;
        }
#pragma unroll
        for (int mt = 0; mt < 4; ++mt) {
#pragma unroll
            for (int half = 0; half < 2; ++half) {
                int m = block_m + warp_m * 64 + mt * 16 + gid + half * 8;
                float v0 = acc[mt][nt][half * 2 + 0] + bi0;
                float v1 = acc[mt][nt][half * 2 + 1] + bi1;
                if (mode == 0) {
                    int b = m >> 11;
                    int t = m & 2047;
                    if (do_rope) {
                        float sn, cs;
                        sincosf((float)t * theta, &sn, &cs);
                        float r0 = v0 * cs - v1 * sn;
                        float r1 = v0 * sn + v1 * cs;
                        v0 = r0; v1 = r1;
                    }
                    float* basep = (r < 64) ? g_Q : ((r < 128) ? g_K : g_V);
                    size_t idx = (((size_t)(b * NH + h) * Tlen) + t) * HS + (r & 63);
                    *(float2*)&basep[idx] = make_float2(v0, v1);
                } else {
                    *(float2*)&outp[(size_t)m * Cdim + n_g] = make_float2(v0, v1);
                }
            }
        }
    }
}

// ---------------------------------------------------------------------------
// Causal flash attention (unchanged): 64 queries/block, 64-key tiles
// ---------------------------------------------------------------------------
#define QS_STRIDE 68
#define PS_STRIDE 68
#define ATTN_SMEM_FLOATS (64 * QS_STRIDE * 2 + 64 * 64 + 64 * PS_STRIDE + 192)

__global__ __launch_bounds__(256) void attn_kernel(
    const float* __restrict__ Q,
    const float* __restrict__ K,
    const float* __restrict__ V,
    float* __restrict__ Y)
{
    extern __shared__ float sm[];
    float* Qs = sm;
    float* Ks = Qs + 64 * QS_STRIDE;
    float* Vs = Ks + 64 * QS_STRIDE;
    float* Ps = Vs + 64 * 64;
    float* m_sh = Ps + 64 * PS_STRIDE;
    float* l_sh = m_sh + 64;
    float* corr = l_sh + 64;

    int tid = threadIdx.x;
    int tx = tid & 15;
    int ty = tid >> 4;
    int warp = tid >> 5;
    int lane = tid & 31;

    int qtile = blockIdx.x;
    int bh = blockIdx.y;

    const float* Qg = Q + ((long)bh * Tlen + qtile * 64) * HS;

    for (int idx = tid; idx < 4096; idx += 256) {
        int mm = idx >> 6, dd = idx & 63;
        Qs[dd * QS_STRIDE + mm] = Qg[idx] * 0.125f;
    }
    if (tid < 64) { m_sh[tid] = -1e30f; l_sh[tid] = 0.0f; }

    float o[4][4];
#pragma unroll
    for (int i = 0; i < 4; i++)
#pragma unroll
        for (int j = 0; j < 4; j++) o[i][j] = 0.0f;

    __syncthreads();

    for (int kt = 0; kt <= qtile; ++kt) {
        const float* Kg = K + ((long)bh * Tlen + kt * 64) * HS;
        const float* Vg = V + ((long)bh * Tlen + kt * 64) * HS;
        for (int idx = tid; idx < 4096; idx += 256) {
            int nn = idx >> 6, dd = idx & 63;
            Ks[dd * QS_STRIDE + nn] = Kg[idx];
            Vs[idx] = Vg[idx];
        }
        __syncthreads();

        float s[4][4];
#pragma unroll
        for (int i = 0; i < 4; i++)
#pragma unroll
            for (int j = 0; j < 4; j++) s[i][j] = 0.0f;
#pragma unroll 4
        for (int d = 0; d < 64; ++d) {
            float4 qa = *(float4*)&Qs[d * QS_STRIDE + ty * 4];
            float4 kb = *(float4*)&Ks[d * QS_STRIDE + tx * 4];
            float qv[4] = {qa.x, qa.y, qa.z, qa.w};
            float kv[4] = {kb.x, kb.y, kb.z, kb.w};
#pragma unroll
            for (int i = 0; i < 4; i++)
#pragma unroll
                for (int j = 0; j < 4; j++) s[i][j] = fmaf(qv[i], kv[j], s[i][j]);
        }

        bool diag = (kt == qtile);
#pragma unroll
        for (int i = 0; i < 4; i++) {
            int m = ty * 4 + i;
            float4 row;
            float* rp = &row.x;
#pragma unroll
            for (int j = 0; j < 4; j++) {
                int n = tx * 4 + j;
                float v = s[i][j];
                if (diag && n > m) v = -1e30f;
                rp[j] = v;
            }
            *(float4*)&Ps[m * PS_STRIDE + tx * 4] = row;
        }
        __syncthreads();

#pragma unroll
        for (int rr = 0; rr < 8; ++rr) {
            int m = warp * 8 + rr;
            float2 sv = *(float2*)&Ps[m * PS_STRIDE + lane * 2];
            float mx = fmaxf(sv.x, sv.y);
#pragma unroll
            for (int off = 16; off; off >>= 1)
                mx = fmaxf(mx, __shfl_xor_sync(0xffffffffu, mx, off));
            float mold = m_sh[m];
            float mnew = fmaxf(mold, mx);
            float e0 = __expf(sv.x - mnew);
            float e1 = __expf(sv.y - mnew);
            *(float2*)&Ps[m * PS_STRIDE + lane * 2] = make_float2(e0, e1);
            float sum = e0 + e1;
#pragma unroll
            for (int off = 16; off; off >>= 1)
                sum += __shfl_xor_sync(0xffffffffu, sum, off);
            if (lane == 0) {
                float cf = __expf(mold - mnew);
                l_sh[m] = l_sh[m] * cf + sum;
                m_sh[m] = mnew;
                corr[m] = cf;
            }
        }
        __syncthreads();

#pragma unroll
        for (int i = 0; i < 4; i++) {
            float cf = corr[ty * 4 + i];
#pragma unroll
            for (int j = 0; j < 4; j++) o[i][j] *= cf;
        }
#pragma unroll 4
        for (int n = 0; n < 64; ++n) {
            float4 vb = *(float4*)&Vs[n * 64 + tx * 4];
            float vv[4] = {vb.x, vb.y, vb.z, vb.w};
            float pv[4];
#pragma unroll
            for (int i = 0; i < 4; i++) pv[i] = Ps[(ty * 4 + i) * PS_STRIDE + n];
#pragma unroll
            for (int i = 0; i < 4; i++)
#pragma unroll
                for (int j = 0; j < 4; j++) o[i][j] = fmaf(pv[i], vv[j], o[i][j]);
        }
        __syncthreads();
    }

    int b = bh >> 4, h = bh & 15;
#pragma unroll
    for (int i = 0; i < 4; i++) {
        int m = ty * 4 + i;
        int t = qtile * 64 + m;
        float inv = 1.0f / l_sh[m];
        long base = ((long)b * Tlen + t) * Cdim + h * HS + tx * 4;
#pragma unroll
        for (int j = 0; j < 4; j++)
            Y[base + j] = o[i][j] * inv;
    }
}

// ---------------------------------------------------------------------------
extern "C" void kernel_launch(void* const* d_in, const int* in_sizes, int n_in,
                              void* d_out, int out_size)
{
    const float* x      = (const float*)d_in[0];
    const float* W_qkv  = (const float*)d_in[1];
    const float* b_qkv  = (const float*)d_in[2];
    const float* W_proj = (const float*)d_in[3];
    const float* b_proj = (const float*)d_in[4];
    float* out = (float*)d_out;

    float *Qp, *Kp, *Vp, *Yp;
    cudaGetSymbolAddress((void**)&Qp, g_Q);
    cudaGetSymbolAddress((void**)&Kp, g_K);
    cudaGetSymbolAddress((void**)&Vp, g_V);
    cudaGetSymbolAddress((void**)&Yp, g_Y);
    __nv_bfloat16 *xhi, *xlo, *wqh, *wql, *wph, *wpl, *yhi, *ylo;
    cudaGetSymbolAddress((void**)&xhi, g_xhi);
    cudaGetSymbolAddress((void**)&xlo, g_xlo);
    cudaGetSymbolAddress((void**)&wqh, g_wqkv_hi);
    cudaGetSymbolAddress((void**)&wql, g_wqkv_lo);
    cudaGetSymbolAddress((void**)&wph, g_wproj_hi);
    cudaGetSymbolAddress((void**)&wpl, g_wproj_lo);
    cudaGetSymbolAddress((void**)&yhi, g_yhi);
    cudaGetSymbolAddress((void**)&ylo, g_ylo);

    int attn_smem = ATTN_SMEM_FLOATS * (int)sizeof(float);
    cudaFuncSetAttribute(attn_kernel, cudaFuncAttributeMaxDynamicSharedMemorySize, attn_smem);
    cudaFuncSetAttribute(gemm_mma, cudaFuncAttributeMaxDynamicSharedMemorySize, GEMM_SMEM);

    // Prep: split x, transpose+split weights
    split_bf16<<<(M_ROWS * Cdim / 4 + 255) / 256, 256>>>(x, xhi, xlo, M_ROWS * Cdim / 4);
    dim3 tgq(N_QKV / 32, Cdim / 32);
    transpose_split<<<tgq, dim3(32, 8)>>>(W_qkv, wqh, wql, Cdim, N_QKV);
    dim3 tgp(Cdim / 32, Cdim / 32);
    transpose_split<<<tgp, dim3(32, 8)>>>(W_proj, wph, wpl, Cdim, Cdim);

    // QKV GEMM + bias + RoPE + scatter
    dim3 g1(N_QKV / 128, M_ROWS / 128);
    gemm_mma<<<g1, 256, GEMM_SMEM>>>(xhi, xlo, wqh, wql, b_qkv, nullptr, 0);

    // Attention
    dim3 g2(Tlen / 64, Bsz * NH);
    attn_kernel<<<g2, 256, attn_smem>>>(Qp, Kp, Vp, Yp);

    // Split Y, proj GEMM
    split_bf16<<<(M_ROWS * Cdim / 4 + 255) / 256, 256>>>(Yp, yhi, ylo, M_ROWS * Cdim / 4);
    dim3 g3(Cdim / 128, M_ROWS / 128);
    gemm_mma<<<g3, 256, GEMM_SMEM>>>(yhi, ylo, wph, wpl, b_proj, out, 1);
}

// round 4
// speedup vs baseline: 2.8200x; 1.9341x over previous
#include <cuda_runtime.h>
#include <cuda_bf16.h>
#include <stdint.h>

// Problem constants
#define Bsz 2
#define Tlen 2048
#define Cdim 1024
#define NH 16
#define HS 64
#define M_ROWS (Bsz * Tlen)        // 4096
#define N_QKV (3 * Cdim)           // 3072
#define NBH (Bsz * NH)             // 32

// ---------------------------------------------------------------------------
// Device scratch (no cudaMalloc allowed)
// ---------------------------------------------------------------------------
__device__ __nv_bfloat16 g_xhi[M_ROWS * Cdim];
__device__ __nv_bfloat16 g_xlo[M_ROWS * Cdim];
__device__ __nv_bfloat16 g_wqkv_hi[N_QKV * Cdim];   // transposed [N][K]
__device__ __nv_bfloat16 g_wqkv_lo[N_QKV * Cdim];
__device__ __nv_bfloat16 g_wproj_hi[Cdim * Cdim];   // transposed [N][K]
__device__ __nv_bfloat16 g_wproj_lo[Cdim * Cdim];

__device__ __nv_bfloat16 g_Qh[NBH * Tlen * HS];
__device__ __nv_bfloat16 g_Ql[NBH * Tlen * HS];
__device__ __nv_bfloat16 g_Kh[NBH * Tlen * HS];
__device__ __nv_bfloat16 g_Kl[NBH * Tlen * HS];
__device__ __nv_bfloat16 g_Vh[NBH * Tlen * HS];
__device__ __nv_bfloat16 g_Vl[NBH * Tlen * HS];

__device__ __nv_bfloat16 g_yhi[M_ROWS * Cdim];
__device__ __nv_bfloat16 g_ylo[M_ROWS * Cdim];

// ---------------------------------------------------------------------------
// Portable PTX helpers (no arch-specific 'a' features)
// ---------------------------------------------------------------------------
__device__ __forceinline__ uint32_t smem_u32(const void* p) {
    uint32_t a;
    asm("{ .reg .u64 t; cvta.to.shared.u64 t, %1; cvt.u32.u64 %0, t; }"
        : "=r"(a) : "l"(p));
    return a;
}
__device__ __forceinline__ void cp16(uint32_t s, const void* g) {
    asm volatile("cp.async.cg.shared.global [%0], [%1], 16;" :: "r"(s), "l"(g));
}
__device__ __forceinline__ void cp_commit() {
    asm volatile("cp.async.commit_group;" ::: "memory");
}
__device__ __forceinline__ void cp_wait1() {
    asm volatile("cp.async.wait_group 1;" ::: "memory");
}
__device__ __forceinline__ void cp_wait0() {
    asm volatile("cp.async.wait_group 0;" ::: "memory");
}
__device__ __forceinline__ void ldm_x4(uint32_t* r, uint32_t addr) {
    asm volatile("ldmatrix.sync.aligned.m8n8.x4.shared.b16 {%0,%1,%2,%3}, [%4];"
                 : "=r"(r[0]), "=r"(r[1]), "=r"(r[2]), "=r"(r[3]) : "r"(addr));
}
__device__ __forceinline__ void ldm_x2(uint32_t* r, uint32_t addr) {
    asm volatile("ldmatrix.sync.aligned.m8n8.x2.shared.b16 {%0,%1}, [%2];"
                 : "=r"(r[0]), "=r"(r[1]) : "r"(addr));
}
__device__ __forceinline__ void ldm_x2_t(uint32_t* r, uint32_t addr) {
    asm volatile("ldmatrix.sync.aligned.m8n8.x2.trans.shared.b16 {%0,%1}, [%2];"
                 : "=r"(r[0]), "=r"(r[1]) : "r"(addr));
}
__device__ __forceinline__ void mma16816(float* c, const uint32_t* a, const uint32_t* b) {
    asm volatile(
        "mma.sync.aligned.m16n8k16.row.col.f32.bf16.bf16.f32 "
        "{%0,%1,%2,%3}, {%4,%5,%6,%7}, {%8,%9}, {%0,%1,%2,%3};"
        : "+f"(c[0]), "+f"(c[1]), "+f"(c[2]), "+f"(c[3])
        : "r"(a[0]), "r"(a[1]), "r"(a[2]), "r"(a[3]), "r"(b[0]), "r"(b[1]));
}
__device__ __forceinline__ uint32_t pack_bf2(float a, float b) {
    __nv_bfloat162 h = __float22bfloat162_rn(make_float2(a, b));
    return *(uint32_t*)&h;
}

// ---------------------------------------------------------------------------
// Prep kernels
// ---------------------------------------------------------------------------
__global__ __launch_bounds__(256) void split_bf16(
    const float* __restrict__ in, __nv_bfloat16* __restrict__ hi,
    __nv_bfloat16* __restrict__ lo, int n4)
{
    int i = blockIdx.x * 256 + threadIdx.x;
    if (i >= n4) return;
    float4 v = ((const float4*)in)[i];
    __nv_bfloat16 h0 = __float2bfloat16(v.x);
    __nv_bfloat16 h1 = __float2bfloat16(v.y);
    __nv_bfloat16 h2 = __float2bfloat16(v.z);
    __nv_bfloat16 h3 = __float2bfloat16(v.w);
    __nv_bfloat162* H = (__nv_bfloat162*)hi;
    __nv_bfloat162* L = (__nv_bfloat162*)lo;
    H[i * 2 + 0] = __nv_bfloat162(h0, h1);
    H[i * 2 + 1] = __nv_bfloat162(h2, h3);
    L[i * 2 + 0] = __nv_bfloat162(__float2bfloat16(v.x - __bfloat162float(h0)),
                                  __float2bfloat16(v.y - __bfloat162float(h1)));
    L[i * 2 + 1] = __nv_bfloat162(__float2bfloat16(v.z - __bfloat162float(h2)),
                                  __float2bfloat16(v.w - __bfloat162float(h3)));
}

// W [K][N] -> Wt hi/lo [N][K]
__global__ __launch_bounds__(256) void transpose_split(
    const float* __restrict__ W, __nv_bfloat16* __restrict__ hi,
    __nv_bfloat16* __restrict__ lo, int K, int N)
{
    __shared__ float t[32][33];
    int n0 = blockIdx.x * 32, k0 = blockIdx.y * 32;
    int tx = threadIdx.x, ty = threadIdx.y;
#pragma unroll
    for (int r = ty; r < 32; r += 8)
        t[r][tx] = W[(size_t)(k0 + r) * N + n0 + tx];
    __syncthreads();
#pragma unroll
    for (int r = ty; r < 32; r += 8) {
        float v = t[tx][r];
        size_t o = (size_t)(n0 + r) * K + k0 + tx;
        __nv_bfloat16 h = __float2bfloat16(v);
        hi[o] = h;
        lo[o] = __float2bfloat16(v - __bfloat162float(h));
    }
}

// ---------------------------------------------------------------------------
// mma.sync GEMM: D[128x128] = Ahi*Bhi + Ahi*Blo + Alo*Bhi   (K = 1024)
// mode 0: bias + RoPE + hi/lo-split scatter to Q/K/V   mode 1: bias + fp32 out
// ---------------------------------------------------------------------------
#define ROWB 80
#define TILEB (128 * ROWB)
#define BUFB  (4 * TILEB)
#define GEMM_SMEM (2 * BUFB)

__global__ __launch_bounds__(256) void gemm_mma(
    const __nv_bfloat16* __restrict__ Ahi,
    const __nv_bfloat16* __restrict__ Alo,
    const __nv_bfloat16* __restrict__ Bhi,
    const __nv_bfloat16* __restrict__ Blo,
    const float* __restrict__ bias,
    float* __restrict__ outp,
    int mode)
{
    extern __shared__ __align__(128) char smc[];
    const uint32_t sbase = smem_u32(smc);
    const int tid = threadIdx.x;
    const int lane = tid & 31;
    const int wid = tid >> 5;
    const int warp_m = wid >> 2;
    const int warp_n = wid & 3;
    const int block_n = blockIdx.x * 128;
    const int block_m = blockIdx.y * 128;

    const char* srcs[4] = {
        (const char*)Ahi + (size_t)block_m * 2048,
        (const char*)Alo + (size_t)block_m * 2048,
        (const char*)Bhi + (size_t)block_n * 2048,
        (const char*)Blo + (size_t)block_n * 2048 };

    float acc[4][4][4];
#pragma unroll
    for (int i = 0; i < 4; i++)
#pragma unroll
        for (int j = 0; j < 4; j++)
#pragma unroll
            for (int k = 0; k < 4; k++) acc[i][j][k] = 0.0f;

    auto load_chunk = [&](int c, int buf) {
        uint32_t db = sbase + buf * BUFB;
        size_t goff = (size_t)c * 64;
#pragma unroll
        for (int it = 0; it < 8; ++it) {
            int i = tid + it * 256;
            int tI = i >> 9;
            int r = (i >> 2) & 127;
            int seg = i & 3;
            cp16(db + tI * TILEB + r * ROWB + seg * 16,
                 srcs[tI] + (size_t)r * 2048 + goff + seg * 16);
        }
        cp_commit();
    };

    load_chunk(0, 0);

    for (int c = 0; c < 32; ++c) {
        int buf = c & 1;
        if (c + 1 < 32) { load_chunk(c + 1, (c + 1) & 1); cp_wait1(); }
        else cp_wait0();
        __syncthreads();

        uint32_t abase = sbase + buf * BUFB;
        uint32_t bbase = abase + 2 * TILEB;
#pragma unroll
        for (int k16 = 0; k16 < 2; ++k16) {
            uint32_t ah[4][4], al[4][4], bh[4][2], bl[4][2];
            int akb = k16 * 32 + ((lane >> 4) & 1) * 16;
            int bkb = k16 * 32 + ((lane >> 3) & 1) * 16;
#pragma unroll
            for (int mt = 0; mt < 4; ++mt) {
                int row = warp_m * 64 + mt * 16 + (lane & 15);
                uint32_t ad = abase + row * ROWB + akb;
                ldm_x4(ah[mt], ad);
                ldm_x4(al[mt], ad + TILEB);
            }
#pragma unroll
            for (int nt = 0; nt < 4; ++nt) {
                int nrow = warp_n * 32 + nt * 8 + (lane & 7);
                uint32_t bd = bbase + nrow * ROWB + bkb;
                ldm_x2(bh[nt], bd);
                ldm_x2(bl[nt], bd + TILEB);
            }
#pragma unroll
            for (int mt = 0; mt < 4; ++mt)
#pragma unroll
                for (int nt = 0; nt < 4; ++nt) {
                    mma16816(acc[mt][nt], ah[mt], bh[nt]);
                    mma16816(acc[mt][nt], ah[mt], bl[nt]);
                    mma16816(acc[mt][nt], al[mt], bh[nt]);
                }
        }
        __syncthreads();
    }

    // --- epilogue ---
    const int gid = lane >> 2;
    const int cpair = (lane & 3) * 2;

#pragma unroll
    for (int nt = 0; nt < 4; ++nt) {
        int n_g = block_n + warp_n * 32 + nt * 8 + cpair;
        float bi0 = bias[n_g], bi1 = bias[n_g + 1];
        int h = n_g / 192;
        int r = n_g - h * 192;
        float theta = 0.0f;
        bool do_rope = false;
        if (mode == 0 && r < 128) {
            int p = (r & 63) >> 1;
            theta = __expf(-(float)p * 0.28782313662425572f);
            do_rope = true;
        }
#pragma unroll
        for (int mt = 0; mt < 4; ++mt) {
#pragma unroll
            for (int half = 0; half < 2; ++half) {
                int m = block_m + warp_m * 64 + mt * 16 + gid + half * 8;
                float v0 = acc[mt][nt][half * 2 + 0] + bi0;
                float v1 = acc[mt][nt][half * 2 + 1] + bi1;
                if (mode == 0) {
                    int b = m >> 11;
                    int t = m & 2047;
                    if (do_rope) {
                        float sn, cs;
                        sincosf((float)t * theta, &sn, &cs);
                        float r0 = v0 * cs - v1 * sn;
                        float r1 = v0 * sn + v1 * cs;
                        v0 = r0; v1 = r1;
                    }
                    if (r < 64) { v0 *= 0.125f; v1 *= 0.125f; }  // fold softmax scale into Q
                    __nv_bfloat16 h0 = __float2bfloat16(v0);
                    __nv_bfloat16 h1 = __float2bfloat16(v1);
                    __nv_bfloat162 hh(h0, h1);
                    __nv_bfloat162 ll(__float2bfloat16(v0 - __bfloat162float(h0)),
                                      __float2bfloat16(v1 - __bfloat162float(h1)));
                    __nv_bfloat16 *ph, *pl;
                    if (r < 64)       { ph = g_Qh; pl = g_Ql; }
                    else if (r < 128) { ph = g_Kh; pl = g_Kl; }
                    else              { ph = g_Vh; pl = g_Vl; }
                    size_t idx = (((size_t)(b * NH + h) * Tlen) + t) * HS + (r & 63);
                    *(__nv_bfloat162*)&ph[idx] = hh;
                    *(__nv_bfloat162*)&pl[idx] = ll;
                } else {
                    *(float2*)&outp[(size_t)m * Cdim + n_g] = make_float2(v0, v1);
                }
            }
        }
    }
}

// ---------------------------------------------------------------------------
// Tensor-core causal flash attention.
// 64 queries/block, 4 warps; key tiles of 64; hi/lo bf16 3-product MMAs.
// Smem tiles [64 rows][72 bf16] (144B stride): Qh Ql Kh Kl Vh Vl.
// ---------------------------------------------------------------------------
#define AT_ROWB 144
#define AT_TILEB (64 * AT_ROWB)          // 9216
#define ATTN_SMEM (6 * AT_TILEB)         // 55296

__global__ __launch_bounds__(128) void attn_mma()
{
    extern __shared__ __align__(128) char sm[];
    const uint32_t sb = smem_u32(sm);
    const int tid = threadIdx.x;
    const int lane = tid & 31;
    const int warp = tid >> 5;
    const int gid = lane >> 2;
    const int qd = lane & 3;

    const int bh = blockIdx.y;
    const int qt = (int)gridDim.x - 1 - (int)blockIdx.x;  // heavy blocks first
    const int q0 = qt * 64;
    const size_t bhoff = (size_t)bh * Tlen * HS;

    // ---- load Q hi/lo tiles (64 x 64, rows of 128B) ----
    {
        const char* qsrc[2] = { (const char*)g_Qh, (const char*)g_Ql };
#pragma unroll
        for (int it = 0; it < 8; ++it) {
            int i = tid + it * 128;
            int tile = i >> 9;
            int row = (i >> 3) & 63;
            int seg = i & 7;
            cp16(sb + tile * AT_TILEB + row * AT_ROWB + seg * 16,
                 qsrc[tile] + (bhoff + (size_t)(q0 + row) * HS) * 2 + seg * 16);
        }
    }
    cp_commit(); cp_wait0(); __syncthreads();

    // ---- preload Q fragments (scale already folded in) ----
    uint32_t qh[4][4], ql[4][4];
#pragma unroll
    for (int kb = 0; kb < 4; ++kb) {
        uint32_t ad = sb + (warp * 16 + (lane & 15)) * AT_ROWB
                    + (kb * 16 + (lane >> 4) * 8) * 2;
        ldm_x4(qh[kb], ad);
        ldm_x4(ql[kb], ad + AT_TILEB);
    }

    float m0 = -1e30f, m1 = -1e30f, l0 = 0.0f, l1 = 0.0f;
    float oc[8][4];
#pragma unroll
    for (int j = 0; j < 8; ++j)
#pragma unroll
        for (int e = 0; e < 4; ++e) oc[j][e] = 0.0f;

    const char* kvsrc[4] = { (const char*)g_Kh, (const char*)g_Kl,
                             (const char*)g_Vh, (const char*)g_Vl };

    for (int kt = 0; kt <= qt; ++kt) {
        // ---- load K/V hi/lo tiles ----
        size_t koff = bhoff + (size_t)kt * 64 * HS;
#pragma unroll
        for (int it = 0; it < 16; ++it) {
            int i = tid + it * 128;
            int tile = i >> 9;
            int row = (i >> 3) & 63;
            int seg = i & 7;
            cp16(sb + (2 + tile) * AT_TILEB + row * AT_ROWB + seg * 16,
                 kvsrc[tile] + (koff + (size_t)row * HS) * 2 + seg * 16);
        }
        cp_commit(); cp_wait0(); __syncthreads();

        // ---- S = Q K^T (3-product hi/lo) ----
        float s[8][4];
#pragma unroll
        for (int j = 0; j < 8; ++j)
#pragma unroll
            for (int e = 0; e < 4; ++e) s[j][e] = 0.0f;

#pragma unroll
        for (int j = 0; j < 8; j += 2) {
#pragma unroll
            for (int kb = 0; kb < 4; ++kb) {
                uint32_t kh4[4], kl4[4];
                uint32_t kd = sb + 2 * AT_TILEB + (j * 8 + (lane & 15)) * AT_ROWB
                            + (kb * 16 + (lane >> 4) * 8) * 2;
                ldm_x4(kh4, kd);
                ldm_x4(kl4, kd + AT_TILEB);
                uint32_t bh0[2] = { kh4[0], kh4[2] };
                uint32_t bh1[2] = { kh4[1], kh4[3] };
                uint32_t bl0[2] = { kl4[0], kl4[2] };
                uint32_t bl1[2] = { kl4[1], kl4[3] };
                mma16816(s[j],     qh[kb], bh0);
                mma16816(s[j],     qh[kb], bl0);
                mma16816(s[j],     ql[kb], bh0);
                mma16816(s[j + 1], qh[kb], bh1);
                mma16816(s[j + 1], qh[kb], bl1);
                mma16816(s[j + 1], ql[kb], bh1);
            }
        }

        // ---- causal mask on diagonal tile ----
        if (kt == qt) {
            int rl0 = warp * 16 + gid;
            int rl1 = rl0 + 8;
#pragma unroll
            for (int j = 0; j < 8; ++j) {
                int c0 = j * 8 + qd * 2;
                if (c0 > rl0)     s[j][0] = -1e30f;
                if (c0 + 1 > rl0) s[j][1] = -1e30f;
                if (c0 > rl1)     s[j][2] = -1e30f;
                if (c0 + 1 > rl1) s[j][3] = -1e30f;
            }
        }

        // ---- online softmax (per-thread rows r0, r1; quad reduction) ----
        float t0 = -1e30f, t1 = -1e30f;
#pragma unroll
        for (int j = 0; j < 8; ++j) {
            t0 = fmaxf(t0, fmaxf(s[j][0], s[j][1]));
            t1 = fmaxf(t1, fmaxf(s[j][2], s[j][3]));
        }
        t0 = fmaxf(t0, __shfl_xor_sync(0xffffffffu, t0, 1));
        t0 = fmaxf(t0, __shfl_xor_sync(0xffffffffu, t0, 2));
        t1 = fmaxf(t1, __shfl_xor_sync(0xffffffffu, t1, 1));
        t1 = fmaxf(t1, __shfl_xor_sync(0xffffffffu, t1, 2));

        float mn0 = fmaxf(m0, t0), mn1 = fmaxf(m1, t1);
        float cf0 = __expf(m0 - mn0), cf1 = __expf(m1 - mn1);
        m0 = mn0; m1 = mn1;

        float rs0 = 0.0f, rs1 = 0.0f;
#pragma unroll
        for (int j = 0; j < 8; ++j) {
            s[j][0] = __expf(s[j][0] - mn0);
            s[j][1] = __expf(s[j][1] - mn0);
            s[j][2] = __expf(s[j][2] - mn1);
            s[j][3] = __expf(s[j][3] - mn1);
            rs0 += s[j][0] + s[j][1];
            rs1 += s[j][2] + s[j][3];
        }
        rs0 += __shfl_xor_sync(0xffffffffu, rs0, 1);
        rs0 += __shfl_xor_sync(0xffffffffu, rs0, 2);
        rs1 += __shfl_xor_sync(0xffffffffu, rs1, 1);
        rs1 += __shfl_xor_sync(0xffffffffu, rs1, 2);
        l0 = l0 * cf0 + rs0;
        l1 = l1 * cf1 + rs1;

#pragma unroll
        for (int j = 0; j < 8; ++j) {
            oc[j][0] *= cf0; oc[j][1] *= cf0;
            oc[j][2] *= cf1; oc[j][3] *= cf1;
        }

        // ---- O += P V (3-product hi/lo), P packed from S fragment ----
#pragma unroll
        for (int kk = 0; kk < 4; ++kk) {
            int j0 = 2 * kk, j1 = 2 * kk + 1;
            // hi fragments
            uint32_t aph[4], apl[4];
            {
                float p00 = s[j0][0], p01 = s[j0][1], p02 = s[j0][2], p03 = s[j0][3];
                float p10 = s[j1][0], p11 = s[j1][1], p12 = s[j1][2], p13 = s[j1][3];
                __nv_bfloat16 h00 = __float2bfloat16(p00), h01 = __float2bfloat16(p01);
                __nv_bfloat16 h02 = __float2bfloat16(p02), h03 = __float2bfloat16(p03);
                __nv_bfloat16 h10 = __float2bfloat16(p10), h11 = __float2bfloat16(p11);
                __nv_bfloat16 h12 = __float2bfloat16(p12), h13 = __float2bfloat16(p13);
                __nv_bfloat162 a0(h00, h01), a1(h02, h03), a2(h10, h11), a3(h12, h13);
                aph[0] = *(uint32_t*)&a0; aph[1] = *(uint32_t*)&a1;
                aph[2] = *(uint32_t*)&a2; aph[3] = *(uint32_t*)&a3;
                apl[0] = pack_bf2(p00 - __bfloat162float(h00), p01 - __bfloat162float(h01));
                apl[1] = pack_bf2(p02 - __bfloat162float(h02), p03 - __bfloat162float(h03));
                apl[2] = pack_bf2(p10 - __bfloat162float(h10), p11 - __bfloat162float(h11));
                apl[3] = pack_bf2(p12 - __bfloat162float(h12), p13 - __bfloat162float(h13));
            }
#pragma unroll
            for (int j = 0; j < 8; ++j) {
                uint32_t vh2[2], vl2[2];
                uint32_t vd = sb + 4 * AT_TILEB + (kk * 16 + (lane & 15)) * AT_ROWB
                            + (j * 8) * 2;
                ldm_x2_t(vh2, vd);
                ldm_x2_t(vl2, vd + AT_TILEB);
                mma16816(oc[j], aph, vh2);
                mma16816(oc[j], aph, vl2);
                mma16816(oc[j], apl, vh2);
            }
        }
        __syncthreads();
    }

    // ---- epilogue: y = O / l, written as hi/lo bf16 into [B,T,C] ----
    float i0 = 1.0f / l0, i1 = 1.0f / l1;
    int b = bh >> 4, hh = bh & 15;
    int tq0 = q0 + warp * 16 + gid;
#pragma unroll
    for (int j = 0; j < 8; ++j) {
        int d = j * 8 + qd * 2;
        size_t o0 = ((size_t)(b * Tlen + tq0)) * Cdim + hh * HS + d;
        size_t o1 = o0 + (size_t)8 * Cdim;
        float y0 = oc[j][0] * i0, y1 = oc[j][1] * i0;
        float y2 = oc[j][2] * i1, y3 = oc[j][3] * i1;
        __nv_bfloat16 a = __float2bfloat16(y0), c = __float2bfloat16(y1);
        __nv_bfloat16 e = __float2bfloat16(y2), f = __float2bfloat16(y3);
        __nv_bfloat162 h0(a, c), h1(e, f);
        __nv_bfloat162 z0(__float2bfloat16(y0 - __bfloat162float(a)),
                          __float2bfloat16(y1 - __bfloat162float(c)));
        __nv_bfloat162 z1(__float2bfloat16(y2 - __bfloat162float(e)),
                          __float2bfloat16(y3 - __bfloat162float(f)));
        *(__nv_bfloat162*)&g_yhi[o0] = h0;
        *(__nv_bfloat162*)&g_ylo[o0] = z0;
        *(__nv_bfloat162*)&g_yhi[o1] = h1;
        *(__nv_bfloat162*)&g_ylo[o1] = z1;
    }
}

// ---------------------------------------------------------------------------
extern "C" void kernel_launch(void* const* d_in, const int* in_sizes, int n_in,
                              void* d_out, int out_size)
{
    const float* x      = (const float*)d_in[0];
    const float* W_qkv  = (const float*)d_in[1];
    const float* b_qkv  = (const float*)d_in[2];
    const float* W_proj = (const float*)d_in[3];
    const float* b_proj = (const float*)d_in[4];
    float* out = (float*)d_out;

    __nv_bfloat16 *xhi, *xlo, *wqh, *wql, *wph, *wpl, *yhi, *ylo;
    cudaGetSymbolAddress((void**)&xhi, g_xhi);
    cudaGetSymbolAddress((void**)&xlo, g_xlo);
    cudaGetSymbolAddress((void**)&wqh, g_wqkv_hi);
    cudaGetSymbolAddress((void**)&wql, g_wqkv_lo);
    cudaGetSymbolAddress((void**)&wph, g_wproj_hi);
    cudaGetSymbolAddress((void**)&wpl, g_wproj_lo);
    cudaGetSymbolAddress((void**)&yhi, g_yhi);
    cudaGetSymbolAddress((void**)&ylo, g_ylo);

    cudaFuncSetAttribute(gemm_mma, cudaFuncAttributeMaxDynamicSharedMemorySize, GEMM_SMEM);
    cudaFuncSetAttribute(attn_mma, cudaFuncAttributeMaxDynamicSharedMemorySize, ATTN_SMEM);

    // Prep
    split_bf16<<<(M_ROWS * Cdim / 4 + 255) / 256, 256>>>(x, xhi, xlo, M_ROWS * Cdim / 4);
    dim3 tgq(N_QKV / 32, Cdim / 32);
    transpose_split<<<tgq, dim3(32, 8)>>>(W_qkv, wqh, wql, Cdim, N_QKV);
    dim3 tgp(Cdim / 32, Cdim / 32);
    transpose_split<<<tgp, dim3(32, 8)>>>(W_proj, wph, wpl, Cdim, Cdim);

    // QKV GEMM + bias + RoPE + hi/lo split scatter
    dim3 g1(N_QKV / 128, M_ROWS / 128);
    gemm_mma<<<g1, 256, GEMM_SMEM>>>(xhi, xlo, wqh, wql, b_qkv, nullptr, 0);

    // Tensor-core attention (writes y hi/lo directly)
    dim3 g2(Tlen / 64, NBH);
    attn_mma<<<g2, 128, ATTN_SMEM>>>();

    // Proj GEMM
    dim3 g3(Cdim / 128, M_ROWS / 128);
    gemm_mma<<<g3, 256, GEMM_SMEM>>>(yhi, ylo, wph, wpl, b_proj, out, 1);
}

// round 5
// speedup vs baseline: 3.3973x; 1.2047x over previous
#include <cuda_runtime.h>
#include <cuda_bf16.h>
#include <stdint.h>

// Problem constants
#define Bsz 2
#define Tlen 2048
#define Cdim 1024
#define NH 16
#define HS 64
#define M_ROWS (Bsz * Tlen)        // 4096
#define N_QKV (3 * Cdim)           // 3072
#define NBH (Bsz * NH)             // 32

// ---------------------------------------------------------------------------
// Device scratch (no cudaMalloc allowed)
// ---------------------------------------------------------------------------
__device__ __nv_bfloat16 g_xhi[M_ROWS * Cdim];
__device__ __nv_bfloat16 g_xlo[M_ROWS * Cdim];
__device__ __nv_bfloat16 g_wqkv_hi[N_QKV * Cdim];   // transposed [N][K]
__device__ __nv_bfloat16 g_wqkv_lo[N_QKV * Cdim];
__device__ __nv_bfloat16 g_wproj_hi[Cdim * Cdim];   // transposed [N][K]
__device__ __nv_bfloat16 g_wproj_lo[Cdim * Cdim];

__device__ __nv_bfloat16 g_Qh[NBH * Tlen * HS];
__device__ __nv_bfloat16 g_Ql[NBH * Tlen * HS];
__device__ __nv_bfloat16 g_Kh[NBH * Tlen * HS];
__device__ __nv_bfloat16 g_Kl[NBH * Tlen * HS];
__device__ __nv_bfloat16 g_Vh[NBH * Tlen * HS];
__device__ __nv_bfloat16 g_Vl[NBH * Tlen * HS];

__device__ __nv_bfloat16 g_yhi[M_ROWS * Cdim];
__device__ __nv_bfloat16 g_ylo[M_ROWS * Cdim];

__device__ float2 g_rope[Tlen * 32];   // cos/sin table

// ---------------------------------------------------------------------------
// Portable PTX helpers (no arch-specific 'a' features)
// ---------------------------------------------------------------------------
__device__ __forceinline__ uint32_t smem_u32(const void* p) {
    uint32_t a;
    asm("{ .reg .u64 t; cvta.to.shared.u64 t, %1; cvt.u32.u64 %0, t; }"
        : "=r"(a) : "l"(p));
    return a;
}
__device__ __forceinline__ void cp16(uint32_t s, const void* g) {
    asm volatile("cp.async.cg.shared.global [%0], [%1], 16;" :: "r"(s), "l"(g));
}
__device__ __forceinline__ void cp_commit() {
    asm volatile("cp.async.commit_group;" ::: "memory");
}
__device__ __forceinline__ void cp_wait1() {
    asm volatile("cp.async.wait_group 1;" ::: "memory");
}
__device__ __forceinline__ void ldm_x4(uint32_t* r, uint32_t addr) {
    asm volatile("ldmatrix.sync.aligned.m8n8.x4.shared.b16 {%0,%1,%2,%3}, [%4];"
                 : "=r"(r[0]), "=r"(r[1]), "=r"(r[2]), "=r"(r[3]) : "r"(addr));
}
__device__ __forceinline__ void ldm_x4_t(uint32_t* r, uint32_t addr) {
    asm volatile("ldmatrix.sync.aligned.m8n8.x4.trans.shared.b16 {%0,%1,%2,%3}, [%4];"
                 : "=r"(r[0]), "=r"(r[1]), "=r"(r[2]), "=r"(r[3]) : "r"(addr));
}
__device__ __forceinline__ void mma16816(float* c, const uint32_t* a, const uint32_t* b) {
    asm volatile(
        "mma.sync.aligned.m16n8k16.row.col.f32.bf16.bf16.f32 "
        "{%0,%1,%2,%3}, {%4,%5,%6,%7}, {%8,%9}, {%0,%1,%2,%3};"
        : "+f"(c[0]), "+f"(c[1]), "+f"(c[2]), "+f"(c[3])
        : "r"(a[0]), "r"(a[1]), "r"(a[2]), "r"(a[3]), "r"(b[0]), "r"(b[1]));
}
__device__ __forceinline__ uint32_t pack_bf2(float a, float b) {
    __nv_bfloat162 h = __float22bfloat162_rn(make_float2(a, b));
    return *(uint32_t*)&h;
}

// ---------------------------------------------------------------------------
// Prep kernels
// ---------------------------------------------------------------------------
__global__ __launch_bounds__(256) void rope_init() {
    int idx = blockIdx.x * 256 + threadIdx.x;   // 65536 total
    int t = idx >> 5, p = idx & 31;
    float theta = expf(-(float)p * 0.28782313662425572f);   // ln(1e4)/32
    float s, c;
    sincosf((float)t * theta, &s, &c);
    g_rope[idx] = make_float2(c, s);
}

__global__ __launch_bounds__(256) void split_bf16(
    const float* __restrict__ in, __nv_bfloat16* __restrict__ hi,
    __nv_bfloat16* __restrict__ lo, int n4)
{
    int i = blockIdx.x * 256 + threadIdx.x;
    if (i >= n4) return;
    float4 v = ((const float4*)in)[i];
    __nv_bfloat16 h0 = __float2bfloat16(v.x);
    __nv_bfloat16 h1 = __float2bfloat16(v.y);
    __nv_bfloat16 h2 = __float2bfloat16(v.z);
    __nv_bfloat16 h3 = __float2bfloat16(v.w);
    __nv_bfloat162* H = (__nv_bfloat162*)hi;
    __nv_bfloat162* L = (__nv_bfloat162*)lo;
    H[i * 2 + 0] = __nv_bfloat162(h0, h1);
    H[i * 2 + 1] = __nv_bfloat162(h2, h3);
    L[i * 2 + 0] = __nv_bfloat162(__float2bfloat16(v.x - __bfloat162float(h0)),
                                  __float2bfloat16(v.y - __bfloat162float(h1)));
    L[i * 2 + 1] = __nv_bfloat162(__float2bfloat16(v.z - __bfloat162float(h2)),
                                  __float2bfloat16(v.w - __bfloat162float(h3)));
}

// W [K][N] -> Wt hi/lo [N][K]
__global__ __launch_bounds__(256) void transpose_split(
    const float* __restrict__ W, __nv_bfloat16* __restrict__ hi,
    __nv_bfloat16* __restrict__ lo, int K, int N)
{
    __shared__ float t[32][33];
    int n0 = blockIdx.x * 32, k0 = blockIdx.y * 32;
    int tx = threadIdx.x, ty = threadIdx.y;
#pragma unroll
    for (int r = ty; r < 32; r += 8)
        t[r][tx] = W[(size_t)(k0 + r) * N + n0 + tx];
    __syncthreads();
#pragma unroll
    for (int r = ty; r < 32; r += 8) {
        float v = t[tx][r];
        size_t o = (size_t)(n0 + r) * K + k0 + tx;
        __nv_bfloat16 h = __float2bfloat16(v);
        hi[o] = h;
        lo[o] = __float2bfloat16(v - __bfloat162float(h));
    }
}

// ---------------------------------------------------------------------------
// mma.sync GEMM: D[128x128] = Ahi*Bhi + Ahi*Blo + Alo*Bhi   (K = 1024)
// 3-stage cp.async pipeline, 1 sync/chunk, XOR-swizzled 64B rows.
// mode 0: bias + RoPE + hi/lo-split scatter to Q/K/V   mode 1: bias + fp32 out
// ---------------------------------------------------------------------------
#define GS_SUB 8192                 // 128 rows x 64B
#define GS_STAGE (4 * GS_SUB)       // Ah, Al, Bh, Bl
#define GEMM_SMEM (3 * GS_STAGE)    // 98304

__global__ __launch_bounds__(256, 2) void gemm_mma(
    const __nv_bfloat16* __restrict__ Ahi,
    const __nv_bfloat16* __restrict__ Alo,
    const __nv_bfloat16* __restrict__ Bhi,
    const __nv_bfloat16* __restrict__ Blo,
    const float* __restrict__ bias,
    float* __restrict__ outp,
    int mode)
{
    extern __shared__ __align__(128) char smc[];
    const uint32_t sbase = smem_u32(smc);
    const int tid = threadIdx.x;
    const int lane = tid & 31;
    const int wid = tid >> 5;
    const int warp_m = wid >> 2;
    const int warp_n = wid & 3;
    const int block_n = blockIdx.x * 128;
    const int block_m = blockIdx.y * 128;

    const char* srcs[4] = {
        (const char*)Ahi + (size_t)block_m * 2048,
        (const char*)Alo + (size_t)block_m * 2048,
        (const char*)Bhi + (size_t)block_n * 2048,
        (const char*)Blo + (size_t)block_n * 2048 };

    float acc[4][4][4];
#pragma unroll
    for (int i = 0; i < 4; i++)
#pragma unroll
        for (int j = 0; j < 4; j++)
#pragma unroll
            for (int k = 0; k < 4; k++) acc[i][j][k] = 0.0f;

    auto load_chunk = [&](int c) {
        uint32_t db = sbase + (c % 3) * GS_STAGE;
        size_t goff = (size_t)c * 64;
#pragma unroll
        for (int it = 0; it < 8; ++it) {
            int i = tid + it * 256;
            int tI = i >> 9;
            int r = (i >> 2) & 127;
            int s = i & 3;
            uint32_t phys = db + tI * GS_SUB + r * 64 + ((s ^ ((r >> 1) & 3)) << 4);
            cp16(phys, srcs[tI] + (size_t)r * 2048 + goff + s * 16);
        }
    };

    load_chunk(0); cp_commit();
    load_chunk(1); cp_commit();

    for (int c = 0; c < 32; ++c) {
        cp_wait1();
        __syncthreads();
        if (c + 2 < 32) load_chunk(c + 2);
        cp_commit();

        uint32_t sb2 = sbase + (c % 3) * GS_STAGE;
#pragma unroll
        for (int k16 = 0; k16 < 2; ++k16) {
            uint32_t ah[4][4], al[4][4], bh[4][2], bl[4][2];
            int sA = k16 * 2 + (lane >> 4);
#pragma unroll
            for (int mt = 0; mt < 4; ++mt) {
                int row = warp_m * 64 + mt * 16 + (lane & 15);
                uint32_t ad = sb2 + row * 64 + ((sA ^ ((row >> 1) & 3)) << 4);
                ldm_x4(ah[mt], ad);
                ldm_x4(al[mt], ad + GS_SUB);
            }
            int sB = k16 * 2 + ((lane >> 3) & 1);
#pragma unroll
            for (int ntp = 0; ntp < 2; ++ntp) {
                int row = warp_n * 32 + ntp * 16 + ((lane >> 4) << 3) + (lane & 7);
                uint32_t bd = sb2 + 2 * GS_SUB + row * 64 + ((sB ^ ((row >> 1) & 3)) << 4);
                uint32_t q4[4], q4l[4];
                ldm_x4(q4, bd);
                ldm_x4(q4l, bd + GS_SUB);
                bh[2 * ntp][0] = q4[0];  bh[2 * ntp][1] = q4[1];
                bh[2 * ntp + 1][0] = q4[2]; bh[2 * ntp + 1][1] = q4[3];
                bl[2 * ntp][0] = q4l[0]; bl[2 * ntp][1] = q4l[1];
                bl[2 * ntp + 1][0] = q4l[2]; bl[2 * ntp + 1][1] = q4l[3];
            }
#pragma unroll
            for (int mt = 0; mt < 4; ++mt)
#pragma unroll
                for (int nt = 0; nt < 4; ++nt) {
                    mma16816(acc[mt][nt], ah[mt], bh[nt]);
                    mma16816(acc[mt][nt], ah[mt], bl[nt]);
                    mma16816(acc[mt][nt], al[mt], bh[nt]);
                }
        }
    }

    // --- epilogue ---
    const int gid = lane >> 2;
    const int cpair = (lane & 3) * 2;

#pragma unroll
    for (int nt = 0; nt < 4; ++nt) {
        int n_g = block_n + warp_n * 32 + nt * 8 + cpair;
        float bi0 = bias[n_g], bi1 = bias[n_g + 1];
        int h = n_g / 192;
        int r = n_g - h * 192;
        int p = (r & 63) >> 1;
        bool do_rope = (mode == 0) && (r < 128);
#pragma unroll
        for (int mt = 0; mt < 4; ++mt) {
#pragma unroll
            for (int half = 0; half < 2; ++half) {
                int m = block_m + warp_m * 64 + mt * 16 + gid + half * 8;
                float v0 = acc[mt][nt][half * 2 + 0] + bi0;
                float v1 = acc[mt][nt][half * 2 + 1] + bi1;
                if (mode == 0) {
                    int b = m >> 11;
                    int t = m & 2047;
                    if (do_rope) {
                        float2 cs = g_rope[(t << 5) + p];
                        float r0 = v0 * cs.x - v1 * cs.y;
                        float r1 = v0 * cs.y + v1 * cs.x;
                        v0 = r0; v1 = r1;
                    }
                    if (r < 64) { v0 *= 0.125f; v1 *= 0.125f; }  // fold softmax scale
                    __nv_bfloat16 h0 = __float2bfloat16(v0);
                    __nv_bfloat16 h1 = __float2bfloat16(v1);
                    __nv_bfloat162 hh(h0, h1);
                    __nv_bfloat162 ll(__float2bfloat16(v0 - __bfloat162float(h0)),
                                      __float2bfloat16(v1 - __bfloat162float(h1)));
                    __nv_bfloat16 *ph, *pl;
                    if (r < 64)       { ph = g_Qh; pl = g_Ql; }
                    else if (r < 128) { ph = g_Kh; pl = g_Kl; }
                    else              { ph = g_Vh; pl = g_Vl; }
                    size_t idx = (((size_t)(b * NH + h) * Tlen) + t) * HS + (r & 63);
                    *(__nv_bfloat162*)&ph[idx] = hh;
                    *(__nv_bfloat162*)&pl[idx] = ll;
                } else {
                    *(float2*)&outp[(size_t)m * Cdim + n_g] = make_float2(v0, v1);
                }
            }
        }
    }
}

// ---------------------------------------------------------------------------
// Tensor-core causal flash attention, 3-stage KV pipeline, 1 sync per tile.
// 64 queries/block, 4 warps. Tiles 64x64 bf16 = 8KB, 128B rows XOR-swizzled.
// smem: Qh Ql (16KB) + 3 stages x (Kh Kl Vh Vl = 32KB) = 112KB.
// ---------------------------------------------------------------------------
#define AT_TILE 8192
#define AT_KV_STAGE (4 * AT_TILE)
#define ATTN_SMEM (2 * AT_TILE + 3 * AT_KV_STAGE)   // 114688

__global__ __launch_bounds__(128, 2) void attn_mma()
{
    extern __shared__ __align__(128) char sm[];
    const uint32_t sb = smem_u32(sm);
    const int tid = threadIdx.x;
    const int lane = tid & 31;
    const int warp = tid >> 5;
    const int gid = lane >> 2;
    const int qd = lane & 3;

    const int bh = blockIdx.y;
    const int qt = (int)gridDim.x - 1 - (int)blockIdx.x;  // heavy blocks first
    const int q0 = qt * 64;
    const size_t bhoff = (size_t)bh * Tlen * HS;

    const char* kvsrc[4] = { (const char*)g_Kh, (const char*)g_Kl,
                             (const char*)g_Vh, (const char*)g_Vl };

    auto load_kv = [&](int kt) {
        uint32_t db = sb + 2 * AT_TILE + (kt % 3) * AT_KV_STAGE;
        size_t koff = bhoff + (size_t)kt * 64 * HS;
#pragma unroll
        for (int it = 0; it < 16; ++it) {
            int i = tid + it * 128;
            int tile = i >> 9;
            int row = (i >> 3) & 63;
            int s = i & 7;
            uint32_t phys = db + tile * AT_TILE + row * 128 + ((s ^ (row & 7)) << 4);
            cp16(phys, kvsrc[tile] + (koff + (size_t)row * HS) * 2 + s * 16);
        }
    };

    // prologue: group 0 = Q + KV(0); group 1 = KV(1)
    {
        const char* qsrc[2] = { (const char*)g_Qh, (const char*)g_Ql };
#pragma unroll
        for (int it = 0; it < 8; ++it) {
            int i = tid + it * 128;
            int tile = i >> 9;
            int row = (i >> 3) & 63;
            int s = i & 7;
            uint32_t phys = sb + tile * AT_TILE + row * 128 + ((s ^ (row & 7)) << 4);
            cp16(phys, qsrc[tile] + (bhoff + (size_t)(q0 + row) * HS) * 2 + s * 16);
        }
    }
    load_kv(0);
    cp_commit();
    if (qt >= 1) load_kv(1);
    cp_commit();

    uint32_t qh[4][4], ql[4][4];
    float m0 = -1e30f, m1 = -1e30f, l0 = 0.0f, l1 = 0.0f;
    float oc[8][4];
#pragma unroll
    for (int j = 0; j < 8; ++j)
#pragma unroll
        for (int e = 0; e < 4; ++e) oc[j][e] = 0.0f;

    for (int kt = 0; kt <= qt; ++kt) {
        cp_wait1();
        __syncthreads();
        if (kt + 2 <= qt) load_kv(kt + 2);
        cp_commit();

        if (kt == 0) {
            // preload Q fragments (scale folded in at qkv epilogue)
#pragma unroll
            for (int kb = 0; kb < 4; ++kb) {
                int row = warp * 16 + (lane & 15);
                int s = kb * 2 + (lane >> 4);
                uint32_t ad = sb + row * 128 + ((s ^ (row & 7)) << 4);
                ldm_x4(qh[kb], ad);
                ldm_x4(ql[kb], ad + AT_TILE);
            }
        }

        uint32_t kvb = sb + 2 * AT_TILE + (kt % 3) * AT_KV_STAGE;

        // ---- S = Q K^T (3-product hi/lo) ----
        float s4[8][4];
#pragma unroll
        for (int j = 0; j < 8; ++j)
#pragma unroll
            for (int e = 0; e < 4; ++e) s4[j][e] = 0.0f;

#pragma unroll
        for (int j = 0; j < 8; j += 2) {
#pragma unroll
            for (int kb = 0; kb < 4; ++kb) {
                int row = j * 8 + (lane & 15);
                int sg = kb * 2 + (lane >> 4);
                uint32_t kd = kvb + row * 128 + ((sg ^ (row & 7)) << 4);
                uint32_t kh4[4], kl4[4];
                ldm_x4(kh4, kd);
                ldm_x4(kl4, kd + AT_TILE);
                uint32_t b0h[2] = { kh4[0], kh4[2] };
                uint32_t b1h[2] = { kh4[1], kh4[3] };
                uint32_t b0l[2] = { kl4[0], kl4[2] };
                uint32_t b1l[2] = { kl4[1], kl4[3] };
                mma16816(s4[j],     qh[kb], b0h);
                mma16816(s4[j],     qh[kb], b0l);
                mma16816(s4[j],     ql[kb], b0h);
                mma16816(s4[j + 1], qh[kb], b1h);
                mma16816(s4[j + 1], qh[kb], b1l);
                mma16816(s4[j + 1], ql[kb], b1h);
            }
        }

        // ---- causal mask on diagonal tile ----
        if (kt == qt) {
            int rl0 = warp * 16 + gid;
            int rl1 = rl0 + 8;
#pragma unroll
            for (int j = 0; j < 8; ++j) {
                int c0 = j * 8 + qd * 2;
                if (c0 > rl0)     s4[j][0] = -1e30f;
                if (c0 + 1 > rl0) s4[j][1] = -1e30f;
                if (c0 > rl1)     s4[j][2] = -1e30f;
                if (c0 + 1 > rl1) s4[j][3] = -1e30f;
            }
        }

        // ---- online softmax ----
        float t0 = -1e30f, t1 = -1e30f;
#pragma unroll
        for (int j = 0; j < 8; ++j) {
            t0 = fmaxf(t0, fmaxf(s4[j][0], s4[j][1]));
            t1 = fmaxf(t1, fmaxf(s4[j][2], s4[j][3]));
        }
        t0 = fmaxf(t0, __shfl_xor_sync(0xffffffffu, t0, 1));
        t0 = fmaxf(t0, __shfl_xor_sync(0xffffffffu, t0, 2));
        t1 = fmaxf(t1, __shfl_xor_sync(0xffffffffu, t1, 1));
        t1 = fmaxf(t1, __shfl_xor_sync(0xffffffffu, t1, 2));

        float mn0 = fmaxf(m0, t0), mn1 = fmaxf(m1, t1);
        float cf0 = __expf(m0 - mn0), cf1 = __expf(m1 - mn1);
        m0 = mn0; m1 = mn1;

        float rs0 = 0.0f, rs1 = 0.0f;
#pragma unroll
        for (int j = 0; j < 8; ++j) {
            s4[j][0] = __expf(s4[j][0] - mn0);
            s4[j][1] = __expf(s4[j][1] - mn0);
            s4[j][2] = __expf(s4[j][2] - mn1);
            s4[j][3] = __expf(s4[j][3] - mn1);
            rs0 += s4[j][0] + s4[j][1];
            rs1 += s4[j][2] + s4[j][3];
        }
        rs0 += __shfl_xor_sync(0xffffffffu, rs0, 1);
        rs0 += __shfl_xor_sync(0xffffffffu, rs0, 2);
        rs1 += __shfl_xor_sync(0xffffffffu, rs1, 1);
        rs1 += __shfl_xor_sync(0xffffffffu, rs1, 2);
        l0 = l0 * cf0 + rs0;
        l1 = l1 * cf1 + rs1;

#pragma unroll
        for (int j = 0; j < 8; ++j) {
            oc[j][0] *= cf0; oc[j][1] *= cf0;
            oc[j][2] *= cf1; oc[j][3] *= cf1;
        }

        // ---- O += P V (3-product hi/lo) ----
#pragma unroll
        for (int kk = 0; kk < 4; ++kk) {
            int j0 = 2 * kk, j1 = 2 * kk + 1;
            uint32_t aph[4], apl[4];
            {
                float p00 = s4[j0][0], p01 = s4[j0][1], p02 = s4[j0][2], p03 = s4[j0][3];
                float p10 = s4[j1][0], p11 = s4[j1][1], p12 = s4[j1][2], p13 = s4[j1][3];
                __nv_bfloat16 h00 = __float2bfloat16(p00), h01 = __float2bfloat16(p01);
                __nv_bfloat16 h02 = __float2bfloat16(p02), h03 = __float2bfloat16(p03);
                __nv_bfloat16 h10 = __float2bfloat16(p10), h11 = __float2bfloat16(p11);
                __nv_bfloat16 h12 = __float2bfloat16(p12), h13 = __float2bfloat16(p13);
                __nv_bfloat162 a0(h00, h01), a1(h02, h03), a2(h10, h11), a3(h12, h13);
                aph[0] = *(uint32_t*)&a0; aph[1] = *(uint32_t*)&a1;
                aph[2] = *(uint32_t*)&a2; aph[3] = *(uint32_t*)&a3;
                apl[0] = pack_bf2(p00 - __bfloat162float(h00), p01 - __bfloat162float(h01));
                apl[1] = pack_bf2(p02 - __bfloat162float(h02), p03 - __bfloat162float(h03));
                apl[2] = pack_bf2(p10 - __bfloat162float(h10), p11 - __bfloat162float(h11));
                apl[3] = pack_bf2(p12 - __bfloat162float(h12), p13 - __bfloat162float(h13));
            }
#pragma unroll
            for (int jp = 0; jp < 4; ++jp) {
                int row = kk * 16 + (lane & 15);
                int sg = jp * 2 + (lane >> 4);
                uint32_t vd = kvb + 2 * AT_TILE + row * 128 + ((sg ^ (row & 7)) << 4);
                uint32_t v4h[4], v4l[4];
                ldm_x4_t(v4h, vd);
                ldm_x4_t(v4l, vd + AT_TILE);
                uint32_t bh0[2] = { v4h[0], v4h[1] };
                uint32_t bl0[2] = { v4l[0], v4l[1] };
                uint32_t bh1[2] = { v4h[2], v4h[3] };
                uint32_t bl1[2] = { v4l[2], v4l[3] };
                mma16816(oc[jp * 2],     aph, bh0);
                mma16816(oc[jp * 2],     aph, bl0);
                mma16816(oc[jp * 2],     apl, bh0);
                mma16816(oc[jp * 2 + 1], aph, bh1);
                mma16816(oc[jp * 2 + 1], aph, bl1);
                mma16816(oc[jp * 2 + 1], apl, bh1);
            }
        }
    }

    // ---- epilogue: y = O / l, written hi/lo bf16 into [B,T,C] ----
    float i0 = 1.0f / l0, i1 = 1.0f / l1;
    int b = bh >> 4, hh = bh & 15;
    int tq0 = q0 + warp * 16 + gid;
#pragma unroll
    for (int j = 0; j < 8; ++j) {
        int d = j * 8 + qd * 2;
        size_t o0 = ((size_t)(b * Tlen + tq0)) * Cdim + hh * HS + d;
        size_t o1 = o0 + (size_t)8 * Cdim;
        float y0 = oc[j][0] * i0, y1 = oc[j][1] * i0;
        float y2 = oc[j][2] * i1, y3 = oc[j][3] * i1;
        __nv_bfloat16 a = __float2bfloat16(y0), c = __float2bfloat16(y1);
        __nv_bfloat16 e = __float2bfloat16(y2), f = __float2bfloat16(y3);
        __nv_bfloat162 h0(a, c), h1(e, f);
        __nv_bfloat162 z0(__float2bfloat16(y0 - __bfloat162float(a)),
                          __float2bfloat16(y1 - __bfloat162float(c)));
        __nv_bfloat162 z1(__float2bfloat16(y2 - __bfloat162float(e)),
                          __float2bfloat16(y3 - __bfloat162float(f)));
        *(__nv_bfloat162*)&g_yhi[o0] = h0;
        *(__nv_bfloat162*)&g_ylo[o0] = z0;
        *(__nv_bfloat162*)&g_yhi[o1] = h1;
        *(__nv_bfloat162*)&g_ylo[o1] = z1;
    }
}

// ---------------------------------------------------------------------------
extern "C" void kernel_launch(void* const* d_in, const int* in_sizes, int n_in,
                              void* d_out, int out_size)
{
    const float* x      = (const float*)d_in[0];
    const float* W_qkv  = (const float*)d_in[1];
    const float* b_qkv  = (const float*)d_in[2];
    const float* W_proj = (const float*)d_in[3];
    const float* b_proj = (const float*)d_in[4];
    float* out = (float*)d_out;

    __nv_bfloat16 *xhi, *xlo, *wqh, *wql, *wph, *wpl, *yhi, *ylo;
    cudaGetSymbolAddress((void**)&xhi, g_xhi);
    cudaGetSymbolAddress((void**)&xlo, g_xlo);
    cudaGetSymbolAddress((void**)&wqh, g_wqkv_hi);
    cudaGetSymbolAddress((void**)&wql, g_wqkv_lo);
    cudaGetSymbolAddress((void**)&wph, g_wproj_hi);
    cudaGetSymbolAddress((void**)&wpl, g_wproj_lo);
    cudaGetSymbolAddress((void**)&yhi, g_yhi);
    cudaGetSymbolAddress((void**)&ylo, g_ylo);

    cudaFuncSetAttribute(gemm_mma, cudaFuncAttributeMaxDynamicSharedMemorySize, GEMM_SMEM);
    cudaFuncSetAttribute(attn_mma, cudaFuncAttributeMaxDynamicSharedMemorySize, ATTN_SMEM);

    // Prep
    rope_init<<<(Tlen * 32) / 256, 256>>>();
    split_bf16<<<(M_ROWS * Cdim / 4 + 255) / 256, 256>>>(x, xhi, xlo, M_ROWS * Cdim / 4);
    dim3 tgq(N_QKV / 32, Cdim / 32);
    transpose_split<<<tgq, dim3(32, 8)>>>(W_qkv, wqh, wql, Cdim, N_QKV);
    dim3 tgp(Cdim / 32, Cdim / 32);
    transpose_split<<<tgp, dim3(32, 8)>>>(W_proj, wph, wpl, Cdim, Cdim);

    // QKV GEMM + bias + RoPE + hi/lo split scatter
    dim3 g1(N_QKV / 128, M_ROWS / 128);
    gemm_mma<<<g1, 256, GEMM_SMEM>>>(xhi, xlo, wqh, wql, b_qkv, nullptr, 0);

    // Tensor-core attention (writes y hi/lo directly)
    dim3 g2(Tlen / 64, NBH);
    attn_mma<<<g2, 128, ATTN_SMEM>>>();

    // Proj GEMM
    dim3 g3(Cdim / 128, M_ROWS / 128);
    gemm_mma<<<g3, 256, GEMM_SMEM>>>(yhi, ylo, wph, wpl, b_proj, out, 1);
}